// round 4
// baseline (speedup 1.0000x reference)
#include <cuda_runtime.h>
#include <cuda_bf16.h>
#include <math.h>
#include <stdint.h>

#define S_    4096
#define D_    768
#define H_    12
#define HD_   64
#define NCLS_ 64
#define FF_   3072
#define WIN_  256
#define NWIN_ 513           /* 2*WIN+1 */
#define NKEY_ (NCLS_ + NWIN_)   /* 577 */
#define LAYERS_ 2

// ---------------- scratch (static device globals; no allocation) ----------------
__device__ float g_h  [S_*D_];
__device__ float g_q  [S_*D_];
__device__ float g_k  [S_*D_];
__device__ float g_v  [S_*D_];
__device__ float g_kg [S_*D_];
__device__ float g_vg [S_*D_];
__device__ float g_out[S_*D_];
__device__ float g_tmp[S_*D_];
__device__ float g_ff [S_*FF_];
__device__ float g_hg [NCLS_*D_];
__device__ float g_qg [NCLS_*D_];
__device__ int   g_glb[S_];

// bf16 hi/lo split buffers
// per-layer transposed weight block: 6*D*D + 2*D*FF elements
#define OFF_WQ   0
#define OFF_WK   589824
#define OFF_WV   1179648
#define OFF_WKG  1769472
#define OFF_WVG  2359296
#define OFF_WO   2949120
#define OFF_WF1  3538944
#define OFF_WF2  5898240
#define WLAYER_  8257536
__device__ __align__(16) __nv_bfloat16 g_wth[2*WLAYER_];
__device__ __align__(16) __nv_bfloat16 g_wtl[2*WLAYER_];
__device__ __align__(16) __nv_bfloat16 g_ah[S_*FF_];
__device__ __align__(16) __nv_bfloat16 g_al[S_*FF_];

static __device__ __forceinline__ uint32_t smem_u32(const void* p) {
    uint32_t a;
    asm("{ .reg .u64 t; cvta.to.shared.u64 t, %1; cvt.u32.u64 %0, t; }" : "=r"(a) : "l"(p));
    return a;
}

#define LDMX4(r0, r1, r2, r3, a) \
    asm volatile("ldmatrix.sync.aligned.m8n8.x4.shared.b16 {%0,%1,%2,%3}, [%4];" \
                 : "=r"(r0), "=r"(r1), "=r"(r2), "=r"(r3) : "r"(a))

#define MMA16816(c, a, b0, b1) \
    asm volatile("mma.sync.aligned.m16n8k16.row.col.f32.bf16.bf16.f32 " \
                 "{%0,%1,%2,%3}, {%4,%5,%6,%7}, {%8,%9}, {%0,%1,%2,%3};" \
                 : "+f"((c)[0]), "+f"((c)[1]), "+f"((c)[2]), "+f"((c)[3]) \
                 : "r"((a)[0]), "r"((a)[1]), "r"((a)[2]), "r"((a)[3]), "r"(b0), "r"(b1))

// ================= HMMA GEMM: C(MxN) = A(MxK) @ W(KxN) + bias =================
// A: hi/lo bf16 row-major [M][K]; W: transposed hi/lo bf16 [N][K].
// 3-way split: C = AhBh + AlBh + AhBl  (fp32 accumulate).
// Block 128x128, BK=32, 8 warps each 32(m) x 64(n).
#define SA_ 40   /* smem row stride in halves (32 + 8 pad) */
__global__ __launch_bounds__(256) void hmma_gemm_kernel(
    const __nv_bfloat16* __restrict__ Ah, const __nv_bfloat16* __restrict__ Al,
    const __nv_bfloat16* __restrict__ Bh, const __nv_bfloat16* __restrict__ Bl,
    const float* __restrict__ bias, float* __restrict__ C,
    int M, int N, int K, int act)
{
    __shared__ __nv_bfloat16 sAh[128 * SA_], sAl[128 * SA_];
    __shared__ __nv_bfloat16 sBh[128 * SA_], sBl[128 * SA_];
    const int tid = threadIdx.x;
    const int lane = tid & 31;
    const int wid = tid >> 5;
    const int wm = wid & 3;          // 4 warps along M (32 rows each)
    const int wn = wid >> 2;         // 2 warps along N (64 cols each)
    const int row0 = blockIdx.y * 128;
    const int col0 = blockIdx.x * 128;

    float acc[2][8][4];
#pragma unroll
    for (int i = 0; i < 2; i++)
#pragma unroll
        for (int j = 0; j < 8; j++)
#pragma unroll
            for (int t = 0; t < 4; t++) acc[i][j][t] = 0.f;

    // precompute ldmatrix smem addresses (byte offsets constant per thread)
    const uint32_t a_off0 = (uint32_t)((wm * 32 + (lane & 15)) * SA_ + (lane >> 4) * 8) * 2;
    const uint32_t b_nrow = (uint32_t)(wn * 64 + ((lane >> 4) & 1) * 8 + (lane & 7));
    const uint32_t b_kcol = (uint32_t)(((lane >> 3) & 1) * 8);
    const uint32_t sAh0 = smem_u32(sAh), sAl0 = smem_u32(sAl);
    const uint32_t sBh0 = smem_u32(sBh), sBl0 = smem_u32(sBl);

    for (int k0 = 0; k0 < K; k0 += 32) {
        // ---- fill smem tiles (each thread: 2 x uint4 per array) ----
#pragma unroll
        for (int vv = 0; vv < 2; vv++) {
            const int vIdx = tid + vv * 256;
            const int r = vIdx >> 2;
            const int c = (vIdx & 3) * 8;
            const size_t ga = (size_t)(row0 + r) * K + k0 + c;
            const size_t gb = (size_t)(col0 + r) * K + k0 + c;
            const int so = r * SA_ + c;
            *reinterpret_cast<uint4*>(sAh + so) = *reinterpret_cast<const uint4*>(Ah + ga);
            *reinterpret_cast<uint4*>(sAl + so) = *reinterpret_cast<const uint4*>(Al + ga);
            *reinterpret_cast<uint4*>(sBh + so) = *reinterpret_cast<const uint4*>(Bh + gb);
            *reinterpret_cast<uint4*>(sBl + so) = *reinterpret_cast<const uint4*>(Bl + gb);
        }
        __syncthreads();

#pragma unroll
        for (int ks = 0; ks < 32; ks += 16) {
            uint32_t ahf[2][4], alf[2][4], bhf[4][4], blf[4][4];
#pragma unroll
            for (int mt = 0; mt < 2; mt++) {
                const uint32_t off = a_off0 + (uint32_t)(mt * 16 * SA_ + ks) * 2;
                LDMX4(ahf[mt][0], ahf[mt][1], ahf[mt][2], ahf[mt][3], sAh0 + off);
                LDMX4(alf[mt][0], alf[mt][1], alf[mt][2], alf[mt][3], sAl0 + off);
            }
#pragma unroll
            for (int np = 0; np < 4; np++) {
                const uint32_t off =
                    (uint32_t)(((b_nrow + np * 16) * SA_) + ks + b_kcol) * 2;
                LDMX4(bhf[np][0], bhf[np][1], bhf[np][2], bhf[np][3], sBh0 + off);
                LDMX4(blf[np][0], blf[np][1], blf[np][2], blf[np][3], sBl0 + off);
            }
            // regs of bXf[np]: {b0(nt=2np), b1(nt=2np), b0(nt=2np+1), b1(nt=2np+1)}
#pragma unroll
            for (int mt = 0; mt < 2; mt++) {
#pragma unroll
                for (int nt = 0; nt < 8; nt++) {
                    const int np = nt >> 1, hh = (nt & 1) * 2;
                    MMA16816(acc[mt][nt], ahf[mt], bhf[np][hh], bhf[np][hh + 1]);
                    MMA16816(acc[mt][nt], alf[mt], bhf[np][hh], bhf[np][hh + 1]);
                    MMA16816(acc[mt][nt], ahf[mt], blf[np][hh], blf[np][hh + 1]);
                }
            }
        }
        __syncthreads();
    }

    // ---- epilogue: bias + (optional gelu), direct global write ----
    const int cbase = col0 + wn * 64 + (lane & 3) * 2;
    const int rbase = row0 + wm * 32 + (lane >> 2);
#pragma unroll
    for (int mt = 0; mt < 2; mt++) {
#pragma unroll
        for (int nt = 0; nt < 8; nt++) {
            const int c = cbase + nt * 8;
#pragma unroll
            for (int half = 0; half < 2; half++) {
                const int r = rbase + mt * 16 + half * 8;
                float v0 = acc[mt][nt][half * 2 + 0] + bias[c];
                float v1 = acc[mt][nt][half * 2 + 1] + bias[c + 1];
                if (act == 1) {
                    float u0 = 0.7978845608028654f * (v0 + 0.044715f * v0 * v0 * v0);
                    v0 = 0.5f * v0 * (1.f + tanhf(u0));
                    float u1 = 0.7978845608028654f * (v1 + 0.044715f * v1 * v1 * v1);
                    v1 = 0.5f * v1 * (1.f + tanhf(u1));
                }
                *reinterpret_cast<float2*>(C + (size_t)r * N + c) = make_float2(v0, v1);
            }
        }
    }
}

// ---------------- hi/lo bf16 split of activations ----------------
__global__ __launch_bounds__(256) void conv_hilo_kernel(
    const float* __restrict__ A, __nv_bfloat16* __restrict__ Ah,
    __nv_bfloat16* __restrict__ Al, int n)
{
    int i = blockIdx.x * 256 + threadIdx.x;
    if (i < n) {
        float v = A[i];
        __nv_bfloat16 h = __float2bfloat16(v);
        Ah[i] = h;
        Al[i] = __float2bfloat16(v - __bfloat162float(h));
    }
}

// ---------------- transpose + hi/lo split of weights: W[K][N] -> T[N][K] ----------------
__global__ __launch_bounds__(256) void transpose_conv_kernel(
    const float* __restrict__ W, __nv_bfloat16* __restrict__ Th,
    __nv_bfloat16* __restrict__ Tl, int K, int N)
{
    __shared__ float t[32][33];
    const int n0 = blockIdx.x * 32, k0 = blockIdx.y * 32;
    const int tx = threadIdx.x & 31, ty = threadIdx.x >> 5;
    for (int r = ty; r < 32; r += 8)
        t[r][tx] = W[(size_t)(k0 + r) * N + n0 + tx];
    __syncthreads();
    for (int r = ty; r < 32; r += 8) {
        float v = t[tx][r];
        __nv_bfloat16 hb = __float2bfloat16(v);
        Th[(size_t)(n0 + r) * K + k0 + tx] = hb;
        Tl[(size_t)(n0 + r) * K + k0 + tx] = __float2bfloat16(v - __bfloat162float(hb));
    }
}

// ---------------- fp32 SGEMM (kept for the tiny qg projection, M=64) ----------------
__global__ __launch_bounds__(256) void sgemm_kernel(
    const float* __restrict__ A, const float* __restrict__ B,
    const float* __restrict__ bias, float* __restrict__ C,
    int M, int N, int K, int act)
{
    __shared__ float As[8][128];
    __shared__ float Bs[8][128];
    const int tid = threadIdx.x;
    const int tx = tid & 15;
    const int ty = tid >> 4;
    const int blockRow = blockIdx.y * 128;
    const int blockCol = blockIdx.x * 128;
    const int aRow = tid >> 1;
    const int aCol = (tid & 1) << 2;
    const int bRow = tid >> 5;
    const int bCol = (tid & 31) << 2;
    float acc[8][8];
#pragma unroll
    for (int i = 0; i < 8; i++)
#pragma unroll
        for (int j = 0; j < 8; j++) acc[i][j] = 0.f;

    for (int k0 = 0; k0 < K; k0 += 8) {
        int gr = blockRow + aRow;
        float4 av = make_float4(0.f, 0.f, 0.f, 0.f);
        if (gr < M)
            av = *reinterpret_cast<const float4*>(A + (size_t)gr * K + k0 + aCol);
        As[aCol + 0][aRow] = av.x;
        As[aCol + 1][aRow] = av.y;
        As[aCol + 2][aRow] = av.z;
        As[aCol + 3][aRow] = av.w;
        float4 bv = *reinterpret_cast<const float4*>(B + (size_t)(k0 + bRow) * N + blockCol + bCol);
        *reinterpret_cast<float4*>(&Bs[bRow][bCol]) = bv;
        __syncthreads();
#pragma unroll
        for (int kk = 0; kk < 8; kk++) {
            float a[8], b[8];
            *reinterpret_cast<float4*>(a)     = *reinterpret_cast<const float4*>(&As[kk][ty * 8]);
            *reinterpret_cast<float4*>(a + 4) = *reinterpret_cast<const float4*>(&As[kk][ty * 8 + 4]);
            *reinterpret_cast<float4*>(b)     = *reinterpret_cast<const float4*>(&Bs[kk][tx * 8]);
            *reinterpret_cast<float4*>(b + 4) = *reinterpret_cast<const float4*>(&Bs[kk][tx * 8 + 4]);
#pragma unroll
            for (int i = 0; i < 8; i++)
#pragma unroll
                for (int j = 0; j < 8; j++) acc[i][j] = fmaf(a[i], b[j], acc[i][j]);
        }
        __syncthreads();
    }
#pragma unroll
    for (int i = 0; i < 8; i++) {
        int r = blockRow + ty * 8 + i;
        if (r >= M) continue;
#pragma unroll
        for (int j = 0; j < 8; j++) {
            int c = blockCol + tx * 8 + j;
            float val = acc[i][j] + bias[c];
            if (act == 1) {
                float u = 0.7978845608028654f * (val + 0.044715f * val * val * val);
                val = 0.5f * val * (1.f + tanhf(u));
            }
            C[(size_t)r * N + c] = val;
        }
    }
}

// ---------------- embedding + layernorm ----------------
__global__ __launch_bounds__(256) void embed_ln_kernel(
    const int* __restrict__ x, const int* __restrict__ segs,
    const float* __restrict__ we, const float* __restrict__ pe, const float* __restrict__ te,
    const float* __restrict__ lns, const float* __restrict__ lnb,
    float* __restrict__ hout)
{
    int s = blockIdx.x;
    int tid = threadIdx.x;
    __shared__ float buf[D_];
    __shared__ float red[256];
    int tok = x[s], seg = segs[s];
    float lsum = 0.f;
    for (int d = tid; d < D_; d += 256) {
        float v = we[(size_t)tok * D_ + d] + pe[(size_t)s * D_ + d] + te[(size_t)seg * D_ + d];
        buf[d] = v;
        lsum += v;
    }
    red[tid] = lsum; __syncthreads();
    for (int o = 128; o > 0; o >>= 1) { if (tid < o) red[tid] += red[tid + o]; __syncthreads(); }
    float mean = red[0] / D_;
    __syncthreads();
    float vsum = 0.f;
    for (int d = tid; d < D_; d += 256) { float t = buf[d] - mean; vsum += t * t; }
    red[tid] = vsum; __syncthreads();
    for (int o = 128; o > 0; o >>= 1) { if (tid < o) red[tid] += red[tid + o]; __syncthreads(); }
    float rstd = rsqrtf(red[0] / D_ + 1e-5f);
    for (int d = tid; d < D_; d += 256)
        hout[(size_t)s * D_ + d] = (buf[d] - mean) * rstd * lns[d] + lnb[d];
}

// ---------------- residual add + layernorm (in-place into h) ----------------
__global__ __launch_bounds__(256) void add_ln_kernel(
    float* __restrict__ h, const float* __restrict__ t,
    const float* __restrict__ lns, const float* __restrict__ lnb)
{
    int s = blockIdx.x;
    int tid = threadIdx.x;
    __shared__ float buf[D_];
    __shared__ float red[256];
    float lsum = 0.f;
    for (int d = tid; d < D_; d += 256) {
        float v = h[(size_t)s * D_ + d] + t[(size_t)s * D_ + d];
        buf[d] = v;
        lsum += v;
    }
    red[tid] = lsum; __syncthreads();
    for (int o = 128; o > 0; o >>= 1) { if (tid < o) red[tid] += red[tid + o]; __syncthreads(); }
    float mean = red[0] / D_;
    __syncthreads();
    float vsum = 0.f;
    for (int d = tid; d < D_; d += 256) { float x = buf[d] - mean; vsum += x * x; }
    red[tid] = vsum; __syncthreads();
    for (int o = 128; o > 0; o >>= 1) { if (tid < o) red[tid] += red[tid + o]; __syncthreads(); }
    float rstd = rsqrtf(red[0] / D_ + 1e-5f);
    for (int d = tid; d < D_; d += 256)
        h[(size_t)s * D_ + d] = (buf[d] - mean) * rstd * lns[d] + lnb[d];
}

// ---------------- global flags ----------------
__global__ void zero_flags_kernel(int* f)
{
    int i = blockIdx.x * 256 + threadIdx.x;
    if (i < S_) f[i] = 0;
}
__global__ void set_flags_kernel(const int* __restrict__ clss, int* f)
{
    if (threadIdx.x < NCLS_) f[clss[threadIdx.x]] = 1;
}
__global__ __launch_bounds__(256) void gather_rows_kernel(
    const float* __restrict__ h, const int* __restrict__ clss, float* __restrict__ hg)
{
    int c = blockIdx.x;
    int gp = clss[c];
    for (int d = threadIdx.x; d < D_; d += 256)
        hg[(size_t)c * D_ + d] = h[(size_t)gp * D_ + d];
}

// ---------------- band + global-key attention: one block per (s, head) ----------------
__global__ __launch_bounds__(128) void band_attn_kernel(
    const float* __restrict__ q, const float* __restrict__ k, const float* __restrict__ v,
    const int* __restrict__ clss, const int* __restrict__ mask_src, const int* __restrict__ glb,
    float* __restrict__ out)
{
    const int s = blockIdx.x;
    const int h = blockIdx.y;
    __shared__ float qs[HD_];
    __shared__ float sc[NKEY_];
    __shared__ int   pos[NKEY_];
    __shared__ float red[128];
    const int tid = threadIdx.x;
    const int lane = tid & 31;
    const int w = tid >> 5;

    if (tid < HD_) qs[tid] = q[((size_t)s * H_ + h) * HD_ + tid] * 0.125f;
    __syncthreads();

    for (int i = w; i < NKEY_; i += 4) {
        int p; bool valid;
        if (i < NCLS_) {
            p = clss[i];
            valid = (mask_src[p] > 0);
        } else {
            p = s - WIN_ + (i - NCLS_);
            valid = (p >= 0 && p < S_ && mask_src[p] > 0 && glb[p] == 0);
        }
        float sdot = 0.f;
        if (valid) {
            const float* kp = k + ((size_t)p * H_ + h) * HD_;
            sdot = qs[lane] * kp[lane] + qs[lane + 32] * kp[lane + 32];
#pragma unroll
            for (int o = 16; o > 0; o >>= 1) sdot += __shfl_xor_sync(0xffffffffu, sdot, o);
        }
        if (lane == 0) { sc[i] = valid ? sdot : -1e30f; pos[i] = valid ? p : -1; }
    }
    __syncthreads();

    float m = -1e30f;
    for (int i = tid; i < NKEY_; i += 128) m = fmaxf(m, sc[i]);
    red[tid] = m; __syncthreads();
    for (int o = 64; o > 0; o >>= 1) { if (tid < o) red[tid] = fmaxf(red[tid], red[tid + o]); __syncthreads(); }
    m = red[0];
    __syncthreads();
    float sum = 0.f;
    for (int i = tid; i < NKEY_; i += 128) {
        float e = __expf(sc[i] - m);
        sc[i] = e;
        sum += e;
    }
    red[tid] = sum; __syncthreads();
    for (int o = 64; o > 0; o >>= 1) { if (tid < o) red[tid] += red[tid + o]; __syncthreads(); }
    float inv = 1.f / red[0];
    __syncthreads();

    int d = tid & 63, half = tid >> 6;
    float acc = 0.f;
    for (int i = half; i < NKEY_; i += 2) {
        int p = pos[i];
        if (p >= 0) acc += sc[i] * v[((size_t)p * H_ + h) * HD_ + d];
    }
    red[tid] = acc; __syncthreads();
    if (tid < 64)
        out[((size_t)s * H_ + h) * HD_ + tid] = (red[tid] + red[tid + 64]) * inv;
}

// ---------------- global-query full attention: one block per (c, head) ----------------
__global__ __launch_bounds__(256) void glb_attn_kernel(
    const float* __restrict__ qg, const float* __restrict__ kg, const float* __restrict__ vg,
    const int* __restrict__ clss, const int* __restrict__ mask_src,
    float* __restrict__ out)
{
    const int c = blockIdx.x;
    const int h = blockIdx.y;
    __shared__ float qs[HD_];
    __shared__ float sc[S_];
    __shared__ float red[256];
    const int tid = threadIdx.x;
    const int lane = tid & 31;
    const int w = tid >> 5;

    if (tid < HD_) qs[tid] = qg[((size_t)c * H_ + h) * HD_ + tid] * 0.125f;
    __syncthreads();

    for (int p = w; p < S_; p += 8) {
        const float* kp = kg + ((size_t)p * H_ + h) * HD_;
        float sdot = qs[lane] * kp[lane] + qs[lane + 32] * kp[lane + 32];
#pragma unroll
        for (int o = 16; o > 0; o >>= 1) sdot += __shfl_xor_sync(0xffffffffu, sdot, o);
        if (lane == 0) sc[p] = (mask_src[p] > 0) ? sdot : -1e30f;
    }
    __syncthreads();

    float m = -1e30f;
    for (int p = tid; p < S_; p += 256) m = fmaxf(m, sc[p]);
    red[tid] = m; __syncthreads();
    for (int o = 128; o > 0; o >>= 1) { if (tid < o) red[tid] = fmaxf(red[tid], red[tid + o]); __syncthreads(); }
    m = red[0];
    __syncthreads();
    float sum = 0.f;
    for (int p = tid; p < S_; p += 256) { float e = __expf(sc[p] - m); sc[p] = e; sum += e; }
    red[tid] = sum; __syncthreads();
    for (int o = 128; o > 0; o >>= 1) { if (tid < o) red[tid] += red[tid + o]; __syncthreads(); }
    float inv = 1.f / red[0];
    __syncthreads();

    int d = tid & 63, quarter = tid >> 6;
    float acc = 0.f;
    for (int p = quarter; p < S_; p += 4)
        acc += sc[p] * vg[((size_t)p * H_ + h) * HD_ + d];
    red[tid] = acc; __syncthreads();
    if (tid < 64) {
        float o = (red[tid] + red[tid + 64] + red[tid + 128] + red[tid + 192]) * inv;
        int gp = clss[c];
        out[((size_t)gp * H_ + h) * HD_ + tid] = o;
    }
}

// ---------------- driver ----------------
static void run_mma(const __nv_bfloat16* ah, const __nv_bfloat16* al,
                    const __nv_bfloat16* bh, const __nv_bfloat16* bl,
                    const float* bias, float* C, int M, int N, int K, int act)
{
    dim3 grid(N / 128, M / 128);
    hmma_gemm_kernel<<<grid, 256>>>(ah, al, bh, bl, bias, C, M, N, K, act);
}

extern "C" void kernel_launch(void* const* d_in, const int* in_sizes, int n_in,
                              void* d_out, int out_size)
{
    (void)in_sizes; (void)n_in;
    const int*   x        = (const int*)d_in[0];
    const int*   mask_src = (const int*)d_in[1];
    const int*   clss     = (const int*)d_in[2];
    const int*   segs     = (const int*)d_in[3];
    const float* word_emb = (const float*)d_in[4];
    const float* pos_emb  = (const float*)d_in[5];
    const float* type_emb = (const float*)d_in[6];
    const float* ln_e_s   = (const float*)d_in[7];
    const float* ln_e_b   = (const float*)d_in[8];
    const float* Wq  = (const float*)d_in[9];   const float* bq  = (const float*)d_in[10];
    const float* Wk  = (const float*)d_in[11];  const float* bk  = (const float*)d_in[12];
    const float* Wv  = (const float*)d_in[13];  const float* bv  = (const float*)d_in[14];
    const float* Wqg = (const float*)d_in[15];  const float* bqg = (const float*)d_in[16];
    const float* Wkg = (const float*)d_in[17];  const float* bkg = (const float*)d_in[18];
    const float* Wvg = (const float*)d_in[19];  const float* bvg = (const float*)d_in[20];
    const float* Wo  = (const float*)d_in[21];  const float* bo  = (const float*)d_in[22];
    const float* ln1_s = (const float*)d_in[23]; const float* ln1_b = (const float*)d_in[24];
    const float* Wf1 = (const float*)d_in[25];  const float* bf1 = (const float*)d_in[26];
    const float* Wf2 = (const float*)d_in[27];  const float* bf2 = (const float*)d_in[28];
    const float* ln2_s = (const float*)d_in[29]; const float* ln2_b = (const float*)d_in[30];

    float *h, *q, *k, *v, *kg, *vg, *outb, *tmp, *ff, *hg, *qg;
    int* glb;
    __nv_bfloat16 *wth, *wtl, *ah, *al;
    cudaGetSymbolAddress((void**)&h,    g_h);
    cudaGetSymbolAddress((void**)&q,    g_q);
    cudaGetSymbolAddress((void**)&k,    g_k);
    cudaGetSymbolAddress((void**)&v,    g_v);
    cudaGetSymbolAddress((void**)&kg,   g_kg);
    cudaGetSymbolAddress((void**)&vg,   g_vg);
    cudaGetSymbolAddress((void**)&outb, g_out);
    cudaGetSymbolAddress((void**)&tmp,  g_tmp);
    cudaGetSymbolAddress((void**)&ff,   g_ff);
    cudaGetSymbolAddress((void**)&hg,   g_hg);
    cudaGetSymbolAddress((void**)&qg,   g_qg);
    cudaGetSymbolAddress((void**)&glb,  g_glb);
    cudaGetSymbolAddress((void**)&wth,  g_wth);
    cudaGetSymbolAddress((void**)&wtl,  g_wtl);
    cudaGetSymbolAddress((void**)&ah,   g_ah);
    cudaGetSymbolAddress((void**)&al,   g_al);

    const size_t DD = (size_t)D_ * D_;
    const size_t DF = (size_t)D_ * FF_;

    // transpose + bf16 hi/lo split of all big weights
    for (int l = 0; l < LAYERS_; l++) {
        const size_t wo = (size_t)l * WLAYER_;
        dim3 gdd(D_ / 32, D_ / 32);
        transpose_conv_kernel<<<gdd, 256>>>(Wq  + l * DD, wth + wo + OFF_WQ,  wtl + wo + OFF_WQ,  D_, D_);
        transpose_conv_kernel<<<gdd, 256>>>(Wk  + l * DD, wth + wo + OFF_WK,  wtl + wo + OFF_WK,  D_, D_);
        transpose_conv_kernel<<<gdd, 256>>>(Wv  + l * DD, wth + wo + OFF_WV,  wtl + wo + OFF_WV,  D_, D_);
        transpose_conv_kernel<<<gdd, 256>>>(Wkg + l * DD, wth + wo + OFF_WKG, wtl + wo + OFF_WKG, D_, D_);
        transpose_conv_kernel<<<gdd, 256>>>(Wvg + l * DD, wth + wo + OFF_WVG, wtl + wo + OFF_WVG, D_, D_);
        transpose_conv_kernel<<<gdd, 256>>>(Wo  + l * DD, wth + wo + OFF_WO,  wtl + wo + OFF_WO,  D_, D_);
        transpose_conv_kernel<<<dim3(FF_ / 32, D_ / 32), 256>>>(Wf1 + l * DF, wth + wo + OFF_WF1, wtl + wo + OFF_WF1, D_, FF_);
        transpose_conv_kernel<<<dim3(D_ / 32, FF_ / 32), 256>>>(Wf2 + l * DF, wth + wo + OFF_WF2, wtl + wo + OFF_WF2, FF_, D_);
    }

    // embedding + LN
    embed_ln_kernel<<<S_, 256>>>(x, segs, word_emb, pos_emb, type_emb, ln_e_s, ln_e_b, h);

    // global flags
    zero_flags_kernel<<<(S_ + 255) / 256, 256>>>(glb);
    set_flags_kernel<<<1, 64>>>(clss, glb);

    for (int l = 0; l < LAYERS_; l++) {
        const size_t wo = (size_t)l * WLAYER_;
        // split h
        conv_hilo_kernel<<<(S_ * D_ + 255) / 256, 256>>>(h, ah, al, S_ * D_);
        // Q K V + global-key/value projections (all use A = h)
        run_mma(ah, al, wth + wo + OFF_WQ,  wtl + wo + OFF_WQ,  bq  + l * D_, q,  S_, D_, D_, 0);
        run_mma(ah, al, wth + wo + OFF_WK,  wtl + wo + OFF_WK,  bk  + l * D_, k,  S_, D_, D_, 0);
        run_mma(ah, al, wth + wo + OFF_WV,  wtl + wo + OFF_WV,  bv  + l * D_, v,  S_, D_, D_, 0);
        run_mma(ah, al, wth + wo + OFF_WKG, wtl + wo + OFF_WKG, bkg + l * D_, kg, S_, D_, D_, 0);
        run_mma(ah, al, wth + wo + OFF_WVG, wtl + wo + OFF_WVG, bvg + l * D_, vg, S_, D_, D_, 0);

        // band + global-key attention (writes all rows of outb)
        band_attn_kernel<<<dim3(S_, H_), 128>>>(q, k, v, clss, mask_src, glb, outb);

        // global-query path (tiny: fp32 sgemm)
        gather_rows_kernel<<<NCLS_, 256>>>(h, clss, hg);
        sgemm_kernel<<<dim3(D_ / 128, 1), 256>>>(hg, Wqg + l * DD, bqg + l * D_, qg, NCLS_, D_, D_, 0);
        glb_attn_kernel<<<dim3(NCLS_, H_), 256>>>(qg, kg, vg, clss, mask_src, outb);

        // output projection + residual LN
        conv_hilo_kernel<<<(S_ * D_ + 255) / 256, 256>>>(outb, ah, al, S_ * D_);
        run_mma(ah, al, wth + wo + OFF_WO, wtl + wo + OFF_WO, bo + l * D_, tmp, S_, D_, D_, 0);
        add_ln_kernel<<<S_, 256>>>(h, tmp, ln1_s + l * D_, ln1_b + l * D_);

        // feed-forward
        conv_hilo_kernel<<<(S_ * D_ + 255) / 256, 256>>>(h, ah, al, S_ * D_);
        run_mma(ah, al, wth + wo + OFF_WF1, wtl + wo + OFF_WF1, bf1 + l * FF_, ff, S_, FF_, D_, 1);
        conv_hilo_kernel<<<(S_ * FF_ + 255) / 256, 256>>>(ff, ah, al, S_ * FF_);
        run_mma(ah, al, wth + wo + OFF_WF2, wtl + wo + OFF_WF2, bf2 + l * D_, tmp, S_, D_, FF_, 0);
        add_ln_kernel<<<S_, 256>>>(h, tmp, ln2_s + l * D_, ln2_b + l * D_);
    }

    cudaMemcpyAsync(d_out, h, (size_t)out_size * sizeof(float), cudaMemcpyDeviceToDevice);
}

// round 5
// speedup vs baseline: 1.8091x; 1.8091x over previous
#include <cuda_runtime.h>
#include <math.h>
#include <stdint.h>

#define S_    4096
#define D_    768
#define H_    12
#define HD_   64
#define NCLS_ 64
#define FF_   3072
#define WIN_  256
#define LAYERS_ 2

// ---------------- scratch (static device globals; no allocation) ----------------
__device__ float g_h  [S_*D_];
__device__ float g_q  [S_*D_];
__device__ float g_k  [S_*D_];
__device__ float g_v  [S_*D_];
__device__ float g_kg [S_*D_];
__device__ float g_vg [S_*D_];
__device__ float g_out[S_*D_];
__device__ float g_tmp[S_*D_];
__device__ float g_ff [S_*FF_];
__device__ float g_hg [NCLS_*D_];
__device__ float g_qg [NCLS_*D_];
__device__ int   g_glb[S_];

// ---------------- fp32 SGEMM: C = A(MxK) @ B(KxN) + bias, optional gelu ----------------
__global__ __launch_bounds__(256) void sgemm_kernel(
    const float* __restrict__ A, const float* __restrict__ B,
    const float* __restrict__ bias, float* __restrict__ C,
    int M, int N, int K, int act)
{
    __shared__ float As[8][128];
    __shared__ float Bs[8][128];
    const int tid = threadIdx.x;
    const int tx = tid & 15;
    const int ty = tid >> 4;
    const int blockRow = blockIdx.y * 128;
    const int blockCol = blockIdx.x * 128;
    const int aRow = tid >> 1;
    const int aCol = (tid & 1) << 2;
    const int bRow = tid >> 5;
    const int bCol = (tid & 31) << 2;
    float acc[8][8];
#pragma unroll
    for (int i = 0; i < 8; i++)
#pragma unroll
        for (int j = 0; j < 8; j++) acc[i][j] = 0.f;

    for (int k0 = 0; k0 < K; k0 += 8) {
        int gr = blockRow + aRow;
        float4 av = make_float4(0.f, 0.f, 0.f, 0.f);
        if (gr < M)
            av = *reinterpret_cast<const float4*>(A + (size_t)gr * K + k0 + aCol);
        As[aCol + 0][aRow] = av.x;
        As[aCol + 1][aRow] = av.y;
        As[aCol + 2][aRow] = av.z;
        As[aCol + 3][aRow] = av.w;
        float4 bv = *reinterpret_cast<const float4*>(B + (size_t)(k0 + bRow) * N + blockCol + bCol);
        *reinterpret_cast<float4*>(&Bs[bRow][bCol]) = bv;
        __syncthreads();
#pragma unroll
        for (int kk = 0; kk < 8; kk++) {
            float a[8], b[8];
            *reinterpret_cast<float4*>(a)     = *reinterpret_cast<const float4*>(&As[kk][ty * 8]);
            *reinterpret_cast<float4*>(a + 4) = *reinterpret_cast<const float4*>(&As[kk][ty * 8 + 4]);
            *reinterpret_cast<float4*>(b)     = *reinterpret_cast<const float4*>(&Bs[kk][tx * 8]);
            *reinterpret_cast<float4*>(b + 4) = *reinterpret_cast<const float4*>(&Bs[kk][tx * 8 + 4]);
#pragma unroll
            for (int i = 0; i < 8; i++)
#pragma unroll
                for (int j = 0; j < 8; j++) acc[i][j] = fmaf(a[i], b[j], acc[i][j]);
        }
        __syncthreads();
    }
#pragma unroll
    for (int i = 0; i < 8; i++) {
        int r = blockRow + ty * 8 + i;
        if (r >= M) continue;
#pragma unroll
        for (int j = 0; j < 8; j++) {
            int c = blockCol + tx * 8 + j;
            float val = acc[i][j] + bias[c];
            if (act == 1) {
                float u = 0.7978845608028654f * (val + 0.044715f * val * val * val);
                val = 0.5f * val * (1.f + tanhf(u));
            }
            C[(size_t)r * N + c] = val;
        }
    }
}

// ---------------- embedding + layernorm ----------------
__global__ __launch_bounds__(256) void embed_ln_kernel(
    const int* __restrict__ x, const int* __restrict__ segs,
    const float* __restrict__ we, const float* __restrict__ pe, const float* __restrict__ te,
    const float* __restrict__ lns, const float* __restrict__ lnb,
    float* __restrict__ hout)
{
    int s = blockIdx.x;
    int tid = threadIdx.x;
    __shared__ float buf[D_];
    __shared__ float red[256];
    int tok = x[s], seg = segs[s];
    float lsum = 0.f;
    for (int d = tid; d < D_; d += 256) {
        float v = we[(size_t)tok * D_ + d] + pe[(size_t)s * D_ + d] + te[(size_t)seg * D_ + d];
        buf[d] = v;
        lsum += v;
    }
    red[tid] = lsum; __syncthreads();
    for (int o = 128; o > 0; o >>= 1) { if (tid < o) red[tid] += red[tid + o]; __syncthreads(); }
    float mean = red[0] / D_;
    __syncthreads();
    float vsum = 0.f;
    for (int d = tid; d < D_; d += 256) { float t = buf[d] - mean; vsum += t * t; }
    red[tid] = vsum; __syncthreads();
    for (int o = 128; o > 0; o >>= 1) { if (tid < o) red[tid] += red[tid + o]; __syncthreads(); }
    float rstd = rsqrtf(red[0] / D_ + 1e-5f);
    for (int d = tid; d < D_; d += 256)
        hout[(size_t)s * D_ + d] = (buf[d] - mean) * rstd * lns[d] + lnb[d];
}

// ---------------- residual add + layernorm (in-place into h) ----------------
__global__ __launch_bounds__(256) void add_ln_kernel(
    float* __restrict__ h, const float* __restrict__ t,
    const float* __restrict__ lns, const float* __restrict__ lnb)
{
    int s = blockIdx.x;
    int tid = threadIdx.x;
    __shared__ float buf[D_];
    __shared__ float red[256];
    float lsum = 0.f;
    for (int d = tid; d < D_; d += 256) {
        float v = h[(size_t)s * D_ + d] + t[(size_t)s * D_ + d];
        buf[d] = v;
        lsum += v;
    }
    red[tid] = lsum; __syncthreads();
    for (int o = 128; o > 0; o >>= 1) { if (tid < o) red[tid] += red[tid + o]; __syncthreads(); }
    float mean = red[0] / D_;
    __syncthreads();
    float vsum = 0.f;
    for (int d = tid; d < D_; d += 256) { float x = buf[d] - mean; vsum += x * x; }
    red[tid] = vsum; __syncthreads();
    for (int o = 128; o > 0; o >>= 1) { if (tid < o) red[tid] += red[tid + o]; __syncthreads(); }
    float rstd = rsqrtf(red[0] / D_ + 1e-5f);
    for (int d = tid; d < D_; d += 256)
        h[(size_t)s * D_ + d] = (buf[d] - mean) * rstd * lns[d] + lnb[d];
}

// ---------------- global flags ----------------
__global__ void zero_flags_kernel(int* f)
{
    int i = blockIdx.x * 256 + threadIdx.x;
    if (i < S_) f[i] = 0;
}
__global__ void set_flags_kernel(const int* __restrict__ clss, int* f)
{
    if (threadIdx.x < NCLS_) f[clss[threadIdx.x]] = 1;
}
__global__ __launch_bounds__(256) void gather_rows_kernel(
    const float* __restrict__ h, const int* __restrict__ clss, float* __restrict__ hg)
{
    int c = blockIdx.x;
    int gp = clss[c];
    for (int d = threadIdx.x; d < D_; d += 256)
        hg[(size_t)c * D_ + d] = h[(size_t)gp * D_ + d];
}

// ================ tiled flash-style band + global-key attention ================
// One block per (64-query chunk, head). Key list per chunk: 640 keys =
// 64 global (clss) + 576 window positions [s0-256, s0+319], in 5 chunks of 128.
// Online softmax across chunks; invalid keys scored -1e30 -> prob 0.
#define BKEY_ 128
#define NCH_  5
#define KS_   132   /* Ksd row stride (floats) */
#define VS_   68    /* Vs  row stride */
#define PS_   72    /* Pkq row stride */
// smem float offsets
#define OF_Q  0
#define OF_K  4096                   /* 64*64 */
#define OF_V  (OF_K + 64*KS_)        /* 4096+8448 = 12544 */
#define OF_P  (OF_V + BKEY_*VS_)     /* 12544+8704 = 21248 */
#define OF_KV (OF_P + BKEY_*PS_)     /* 21248+9216 = 30464 */
#define OF_SC (OF_KV + BKEY_)        /* 30592 */
#define OF_SI (OF_SC + 64)           /* 30656 */
#define BAND_SMEM ((OF_SI + 64) * 4) /* 122880 bytes */

__global__ __launch_bounds__(256) void band_attn_tiled_kernel(
    const float* __restrict__ q, const float* __restrict__ k, const float* __restrict__ v,
    const int* __restrict__ clss, const int* __restrict__ mask_src, const int* __restrict__ glb,
    float* __restrict__ out)
{
    extern __shared__ float sm[];
    float* Qsd = sm + OF_Q;          // [d][r]  (transposed, stride 64)
    float* Ksd = sm + OF_K;          // [d][kk] (transposed, stride KS_)
    float* Vs  = sm + OF_V;          // [kk][d] (stride VS_)
    float* Pkq = sm + OF_P;          // [kk][r] (stride PS_)
    int*   kvl = (int*)(sm + OF_KV); // key validity
    float* ssc = sm + OF_SC;         // per-query rescale
    float* sin_ = sm + OF_SI;        // per-query 1/sum

    const int c = blockIdx.x, hh = blockIdx.y;
    const int s0 = c * 64;
    const int t = threadIdx.x;
    const int w = t >> 5, lane = t & 31;

    // load Q (transposed, pre-scaled)
    for (int idx = t; idx < 64 * 16; idx += 256) {
        const int r = idx >> 4, seg = (idx & 15) * 4;
        const float4 qv = *reinterpret_cast<const float4*>(
            q + ((size_t)(s0 + r) * H_ + hh) * HD_ + seg);
        Qsd[(seg + 0) * 64 + r] = qv.x * 0.125f;
        Qsd[(seg + 1) * 64 + r] = qv.y * 0.125f;
        Qsd[(seg + 2) * 64 + r] = qv.z * 0.125f;
        Qsd[(seg + 3) * 64 + r] = qv.w * 0.125f;
    }

    float mstate = -1e30f, ssum = 0.f;   // live in threads t<64
    float O[8][2];
#pragma unroll
    for (int j = 0; j < 8; j++) { O[j][0] = 0.f; O[j][1] = 0.f; }

    const int tq = t >> 4, tk = t & 15;
    const int r0 = tq * 4, kk0 = tk * 8;

    for (int ch = 0; ch < NCH_; ch++) {
        // ---- load K (transposed), V, validity ----
        for (int idx = t; idx < BKEY_ * 16; idx += 256) {
            const int kr = idx >> 4, seg = (idx & 15) * 4;
            const int gi = ch * BKEY_ + kr;
            int p; int val;
            if (gi < NCLS_) {
                p = clss[gi];
                val = (mask_src[p] > 0);
            } else {
                p = s0 + gi - 320;
                val = (p >= 0 && p < S_);
                if (val) val = (mask_src[p] > 0) && (glb[p] == 0);
                if (!val) p = 0;
            }
            if ((idx & 15) == 0) kvl[kr] = val;
            const float4 kv = *reinterpret_cast<const float4*>(
                k + ((size_t)p * H_ + hh) * HD_ + seg);
            Ksd[(seg + 0) * KS_ + kr] = kv.x;
            Ksd[(seg + 1) * KS_ + kr] = kv.y;
            Ksd[(seg + 2) * KS_ + kr] = kv.z;
            Ksd[(seg + 3) * KS_ + kr] = kv.w;
            *reinterpret_cast<float4*>(Vs + kr * VS_ + seg) =
                *reinterpret_cast<const float4*>(v + ((size_t)p * H_ + hh) * HD_ + seg);
        }
        __syncthreads();

        // ---- QK scores: thread computes 4q x 8k ----
        float sc[4][8];
#pragma unroll
        for (int j = 0; j < 4; j++)
#pragma unroll
            for (int i = 0; i < 8; i++) sc[j][i] = 0.f;
#pragma unroll 8
        for (int d = 0; d < 64; d++) {
            const float4 a = *reinterpret_cast<const float4*>(Qsd + d * 64 + r0);
            const float4 b0 = *reinterpret_cast<const float4*>(Ksd + d * KS_ + kk0);
            const float4 b1 = *reinterpret_cast<const float4*>(Ksd + d * KS_ + kk0 + 4);
            const float aa[4] = {a.x, a.y, a.z, a.w};
            const float bb[8] = {b0.x, b0.y, b0.z, b0.w, b1.x, b1.y, b1.z, b1.w};
#pragma unroll
            for (int j = 0; j < 4; j++)
#pragma unroll
                for (int i = 0; i < 8; i++) sc[j][i] = fmaf(aa[j], bb[i], sc[j][i]);
        }
#pragma unroll
        for (int i = 0; i < 8; i++) {
            const int gi = ch * BKEY_ + kk0 + i;
            const int kvalid = kvl[kk0 + i];
#pragma unroll
            for (int j = 0; j < 4; j++) {
                const int r = r0 + j;
                const bool ok = kvalid &&
                    (gi < NCLS_ || (r >= gi - 576 && r <= gi - 64));
                Pkq[(kk0 + i) * PS_ + r] = ok ? sc[j][i] : -1e30f;
            }
        }
        __syncthreads();

        // ---- online softmax update (threads < 64, one per query) ----
        if (t < 64) {
            float mn = mstate;
            for (int kk = 0; kk < BKEY_; kk++) mn = fmaxf(mn, Pkq[kk * PS_ + t]);
            const float scale = (mn <= -1e29f) ? 1.f : __expf(mstate - mn);
            float ls = 0.f;
            for (int kk = 0; kk < BKEY_; kk++) {
                const float sv = Pkq[kk * PS_ + t];
                const float pv = (sv <= -1e29f) ? 0.f : __expf(sv - mn);
                Pkq[kk * PS_ + t] = pv;
                ls += pv;
            }
            ssum = ssum * scale + ls;
            mstate = mn;
            ssc[t] = scale;
        }
        __syncthreads();

        // ---- PV accumulate: warp handles queries w*8..w*8+7, lane dims {lane, lane+32} ----
        {
#pragma unroll
            for (int j = 0; j < 8; j++) {
                const float scj = ssc[w * 8 + j];
                O[j][0] *= scj; O[j][1] *= scj;
            }
            for (int kk = 0; kk < BKEY_; kk++) {
                const float4 pa = *reinterpret_cast<const float4*>(Pkq + kk * PS_ + w * 8);
                const float4 pb = *reinterpret_cast<const float4*>(Pkq + kk * PS_ + w * 8 + 4);
                const float v0 = Vs[kk * VS_ + lane];
                const float v1 = Vs[kk * VS_ + lane + 32];
                O[0][0] = fmaf(pa.x, v0, O[0][0]); O[0][1] = fmaf(pa.x, v1, O[0][1]);
                O[1][0] = fmaf(pa.y, v0, O[1][0]); O[1][1] = fmaf(pa.y, v1, O[1][1]);
                O[2][0] = fmaf(pa.z, v0, O[2][0]); O[2][1] = fmaf(pa.z, v1, O[2][1]);
                O[3][0] = fmaf(pa.w, v0, O[3][0]); O[3][1] = fmaf(pa.w, v1, O[3][1]);
                O[4][0] = fmaf(pb.x, v0, O[4][0]); O[4][1] = fmaf(pb.x, v1, O[4][1]);
                O[5][0] = fmaf(pb.y, v0, O[5][0]); O[5][1] = fmaf(pb.y, v1, O[5][1]);
                O[6][0] = fmaf(pb.z, v0, O[6][0]); O[6][1] = fmaf(pb.z, v1, O[6][1]);
                O[7][0] = fmaf(pb.w, v0, O[7][0]); O[7][1] = fmaf(pb.w, v1, O[7][1]);
            }
        }
        __syncthreads();
    }

    if (t < 64) sin_[t] = 1.f / ssum;
    __syncthreads();
#pragma unroll
    for (int j = 0; j < 8; j++) {
        const int qr = w * 8 + j;
        const float inv = sin_[qr];
        float* op = out + ((size_t)(s0 + qr) * H_ + hh) * HD_;
        op[lane]      = O[j][0] * inv;
        op[lane + 32] = O[j][1] * inv;
    }
}

// ---------------- global-query full attention: one block per (c, head) ----------------
__global__ __launch_bounds__(256) void glb_attn_kernel(
    const float* __restrict__ qg, const float* __restrict__ kg, const float* __restrict__ vg,
    const int* __restrict__ clss, const int* __restrict__ mask_src,
    float* __restrict__ out)
{
    const int c = blockIdx.x;
    const int h = blockIdx.y;
    __shared__ float qs[HD_];
    __shared__ float sc[S_];
    __shared__ float red[256];
    const int tid = threadIdx.x;
    const int lane = tid & 31;
    const int w = tid >> 5;

    if (tid < HD_) qs[tid] = qg[((size_t)c * H_ + h) * HD_ + tid] * 0.125f;
    __syncthreads();

    for (int p = w; p < S_; p += 8) {
        const float* kp = kg + ((size_t)p * H_ + h) * HD_;
        float sdot = qs[lane] * kp[lane] + qs[lane + 32] * kp[lane + 32];
#pragma unroll
        for (int o = 16; o > 0; o >>= 1) sdot += __shfl_xor_sync(0xffffffffu, sdot, o);
        if (lane == 0) sc[p] = (mask_src[p] > 0) ? sdot : -1e30f;
    }
    __syncthreads();

    float m = -1e30f;
    for (int p = tid; p < S_; p += 256) m = fmaxf(m, sc[p]);
    red[tid] = m; __syncthreads();
    for (int o = 128; o > 0; o >>= 1) { if (tid < o) red[tid] = fmaxf(red[tid], red[tid + o]); __syncthreads(); }
    m = red[0];
    __syncthreads();
    float sum = 0.f;
    for (int p = tid; p < S_; p += 256) { float e = __expf(sc[p] - m); sc[p] = e; sum += e; }
    red[tid] = sum; __syncthreads();
    for (int o = 128; o > 0; o >>= 1) { if (tid < o) red[tid] += red[tid + o]; __syncthreads(); }
    float inv = 1.f / red[0];
    __syncthreads();

    int d = tid & 63, quarter = tid >> 6;
    float acc = 0.f;
    for (int p = quarter; p < S_; p += 4)
        acc += sc[p] * vg[((size_t)p * H_ + h) * HD_ + d];
    red[tid] = acc; __syncthreads();
    if (tid < 64) {
        float o = (red[tid] + red[tid + 64] + red[tid + 128] + red[tid + 192]) * inv;
        int gp = clss[c];
        out[((size_t)gp * H_ + h) * HD_ + tid] = o;
    }
}

// ---------------- driver ----------------
static void run_gemm(const float* A, const float* B, const float* bias, float* C,
                     int M, int N, int K, int act)
{
    dim3 grid(N / 128, (M + 127) / 128);
    sgemm_kernel<<<grid, 256>>>(A, B, bias, C, M, N, K, act);
}

extern "C" void kernel_launch(void* const* d_in, const int* in_sizes, int n_in,
                              void* d_out, int out_size)
{
    (void)in_sizes; (void)n_in;
    const int*   x        = (const int*)d_in[0];
    const int*   mask_src = (const int*)d_in[1];
    const int*   clss     = (const int*)d_in[2];
    const int*   segs     = (const int*)d_in[3];
    const float* word_emb = (const float*)d_in[4];
    const float* pos_emb  = (const float*)d_in[5];
    const float* type_emb = (const float*)d_in[6];
    const float* ln_e_s   = (const float*)d_in[7];
    const float* ln_e_b   = (const float*)d_in[8];
    const float* Wq  = (const float*)d_in[9];   const float* bq  = (const float*)d_in[10];
    const float* Wk  = (const float*)d_in[11];  const float* bk  = (const float*)d_in[12];
    const float* Wv  = (const float*)d_in[13];  const float* bv  = (const float*)d_in[14];
    const float* Wqg = (const float*)d_in[15];  const float* bqg = (const float*)d_in[16];
    const float* Wkg = (const float*)d_in[17];  const float* bkg = (const float*)d_in[18];
    const float* Wvg = (const float*)d_in[19];  const float* bvg = (const float*)d_in[20];
    const float* Wo  = (const float*)d_in[21];  const float* bo  = (const float*)d_in[22];
    const float* ln1_s = (const float*)d_in[23]; const float* ln1_b = (const float*)d_in[24];
    const float* Wf1 = (const float*)d_in[25];  const float* bf1 = (const float*)d_in[26];
    const float* Wf2 = (const float*)d_in[27];  const float* bf2 = (const float*)d_in[28];
    const float* ln2_s = (const float*)d_in[29]; const float* ln2_b = (const float*)d_in[30];

    float *h, *q, *k, *v, *kg, *vg, *outb, *tmp, *ff, *hg, *qg;
    int* glb;
    cudaGetSymbolAddress((void**)&h,    g_h);
    cudaGetSymbolAddress((void**)&q,    g_q);
    cudaGetSymbolAddress((void**)&k,    g_k);
    cudaGetSymbolAddress((void**)&v,    g_v);
    cudaGetSymbolAddress((void**)&kg,   g_kg);
    cudaGetSymbolAddress((void**)&vg,   g_vg);
    cudaGetSymbolAddress((void**)&outb, g_out);
    cudaGetSymbolAddress((void**)&tmp,  g_tmp);
    cudaGetSymbolAddress((void**)&ff,   g_ff);
    cudaGetSymbolAddress((void**)&hg,   g_hg);
    cudaGetSymbolAddress((void**)&qg,   g_qg);
    cudaGetSymbolAddress((void**)&glb,  g_glb);

    cudaFuncSetAttribute(band_attn_tiled_kernel,
                         cudaFuncAttributeMaxDynamicSharedMemorySize, BAND_SMEM);

    // embedding + LN
    embed_ln_kernel<<<S_, 256>>>(x, segs, word_emb, pos_emb, type_emb, ln_e_s, ln_e_b, h);

    // global flags
    zero_flags_kernel<<<(S_ + 255) / 256, 256>>>(glb);
    set_flags_kernel<<<1, 64>>>(clss, glb);

    const size_t DD = (size_t)D_ * D_;
    for (int l = 0; l < LAYERS_; l++) {
        // Q K V projections
        run_gemm(h, Wq + l * DD, bq + l * D_, q, S_, D_, D_, 0);
        run_gemm(h, Wk + l * DD, bk + l * D_, k, S_, D_, D_, 0);
        run_gemm(h, Wv + l * DD, bv + l * D_, v, S_, D_, D_, 0);

        // tiled band + global-key attention (writes all rows of outb)
        band_attn_tiled_kernel<<<dim3(S_ / 64, H_), 256, BAND_SMEM>>>(
            q, k, v, clss, mask_src, glb, outb);

        // global-query path
        gather_rows_kernel<<<NCLS_, 256>>>(h, clss, hg);
        sgemm_kernel<<<dim3(D_ / 128, 1), 256>>>(hg, Wqg + l * DD, bqg + l * D_, qg, NCLS_, D_, D_, 0);
        run_gemm(h, Wkg + l * DD, bkg + l * D_, kg, S_, D_, D_, 0);
        run_gemm(h, Wvg + l * DD, bvg + l * D_, vg, S_, D_, D_, 0);
        glb_attn_kernel<<<dim3(NCLS_, H_), 256>>>(qg, kg, vg, clss, mask_src, outb);

        // output projection + residual LN
        run_gemm(outb, Wo + l * DD, bo + l * D_, tmp, S_, D_, D_, 0);
        add_ln_kernel<<<S_, 256>>>(h, tmp, ln1_s + l * D_, ln1_b + l * D_);

        // feed-forward
        run_gemm(h,  Wf1 + (size_t)l * D_ * FF_, bf1 + l * FF_, ff,  S_, FF_, D_, 1);
        run_gemm(ff, Wf2 + (size_t)l * D_ * FF_, bf2 + l * D_,  tmp, S_, D_, FF_, 0);
        add_ln_kernel<<<S_, 256>>>(h, tmp, ln2_s + l * D_, ln2_b + l * D_);
    }

    cudaMemcpyAsync(d_out, h, (size_t)out_size * sizeof(float), cudaMemcpyDeviceToDevice);
}

// round 6
// speedup vs baseline: 1.9477x; 1.0766x over previous
#include <cuda_runtime.h>
#include <math.h>
#include <stdint.h>

#define S_    4096
#define D_    768
#define H_    12
#define HD_   64
#define NCLS_ 64
#define FF_   3072
#define WIN_  256
#define LAYERS_ 2

// ---------------- scratch (static device globals; no allocation) ----------------
__device__ float g_h  [S_*D_];
__device__ float g_q  [S_*D_];
__device__ float g_k  [S_*D_];
__device__ float g_v  [S_*D_];
__device__ float g_kg [S_*D_];
__device__ float g_vg [S_*D_];
__device__ float g_out[S_*D_];
__device__ float g_tmp[S_*D_];
__device__ float g_ff [S_*FF_];
__device__ float g_hg [NCLS_*D_];
__device__ float g_qg [NCLS_*D_];
__device__ int   g_glb[S_];

// ---------------- fp32 SGEMM: C = A(MxK) @ B(KxN) + bias, optional gelu ----------------
// 128x128 tile, BK=16, double-buffered smem + register prefetch, 1 sync/iter.
#define BK_   16
#define SAS_  132   /* padded A-tile k-row stride (floats), 16B-aligned */
__global__ __launch_bounds__(256) void sgemm_kernel(
    const float* __restrict__ A, const float* __restrict__ B,
    const float* __restrict__ bias, float* __restrict__ C,
    int M, int N, int K, int act)
{
    __shared__ float As[2][BK_ * SAS_];
    __shared__ float Bs[2][BK_ * 128];
    const int tid = threadIdx.x;
    const int tx = tid & 15;
    const int ty = tid >> 4;
    const int blockRow = blockIdx.y * 128;
    const int blockCol = blockIdx.x * 128;
    // A loads: each thread 2 consecutive float4 (8 floats) of one row
    const int aRow = tid >> 1;
    const int aCol = (tid & 1) * 8;
    // B loads: each thread 2 consecutive float4 of one k-row
    const int bRow = tid >> 4;
    const int bCol = (tid & 15) * 8;

    float acc[8][8];
#pragma unroll
    for (int i = 0; i < 8; i++)
#pragma unroll
        for (int j = 0; j < 8; j++) acc[i][j] = 0.f;

    const float* Ap = A + (size_t)(blockRow + aRow) * K + aCol;
    const float* Bp = B + (size_t)bRow * N + blockCol + bCol;
    const bool aOk = (blockRow + aRow) < M;

    float4 pa0, pa1, pb0, pb1;
    // ---- preload tile 0 ----
    pa0 = make_float4(0.f, 0.f, 0.f, 0.f); pa1 = pa0;
    if (aOk) { pa0 = *reinterpret_cast<const float4*>(Ap);
               pa1 = *reinterpret_cast<const float4*>(Ap + 4); }
    pb0 = *reinterpret_cast<const float4*>(Bp);
    pb1 = *reinterpret_cast<const float4*>(Bp + 4);
    {
        float* as = As[0];
        as[(aCol + 0) * SAS_ + aRow] = pa0.x;
        as[(aCol + 1) * SAS_ + aRow] = pa0.y;
        as[(aCol + 2) * SAS_ + aRow] = pa0.z;
        as[(aCol + 3) * SAS_ + aRow] = pa0.w;
        as[(aCol + 4) * SAS_ + aRow] = pa1.x;
        as[(aCol + 5) * SAS_ + aRow] = pa1.y;
        as[(aCol + 6) * SAS_ + aRow] = pa1.z;
        as[(aCol + 7) * SAS_ + aRow] = pa1.w;
        *reinterpret_cast<float4*>(Bs[0] + bRow * 128 + bCol) = pb0;
        *reinterpret_cast<float4*>(Bs[0] + bRow * 128 + bCol + 4) = pb1;
    }
    __syncthreads();

    int s = 0;
    for (int k0 = BK_; k0 < K; k0 += BK_) {
        // prefetch next tile into registers
        pa0 = make_float4(0.f, 0.f, 0.f, 0.f); pa1 = pa0;
        if (aOk) { pa0 = *reinterpret_cast<const float4*>(Ap + k0);
                   pa1 = *reinterpret_cast<const float4*>(Ap + k0 + 4); }
        pb0 = *reinterpret_cast<const float4*>(Bp + (size_t)k0 * N);
        pb1 = *reinterpret_cast<const float4*>(Bp + (size_t)k0 * N + 4);

        // compute current tile
        const float* as = As[s];
        const float* bs = Bs[s];
#pragma unroll
        for (int kk = 0; kk < BK_; kk++) {
            float a[8], b[8];
            *reinterpret_cast<float4*>(a)     = *reinterpret_cast<const float4*>(as + kk * SAS_ + ty * 8);
            *reinterpret_cast<float4*>(a + 4) = *reinterpret_cast<const float4*>(as + kk * SAS_ + ty * 8 + 4);
            *reinterpret_cast<float4*>(b)     = *reinterpret_cast<const float4*>(bs + kk * 128 + tx * 8);
            *reinterpret_cast<float4*>(b + 4) = *reinterpret_cast<const float4*>(bs + kk * 128 + tx * 8 + 4);
#pragma unroll
            for (int i = 0; i < 8; i++)
#pragma unroll
                for (int j = 0; j < 8; j++) acc[i][j] = fmaf(a[i], b[j], acc[i][j]);
        }

        // store prefetched tile into the other buffer
        float* asn = As[s ^ 1];
        asn[(aCol + 0) * SAS_ + aRow] = pa0.x;
        asn[(aCol + 1) * SAS_ + aRow] = pa0.y;
        asn[(aCol + 2) * SAS_ + aRow] = pa0.z;
        asn[(aCol + 3) * SAS_ + aRow] = pa0.w;
        asn[(aCol + 4) * SAS_ + aRow] = pa1.x;
        asn[(aCol + 5) * SAS_ + aRow] = pa1.y;
        asn[(aCol + 6) * SAS_ + aRow] = pa1.z;
        asn[(aCol + 7) * SAS_ + aRow] = pa1.w;
        *reinterpret_cast<float4*>(Bs[s ^ 1] + bRow * 128 + bCol) = pb0;
        *reinterpret_cast<float4*>(Bs[s ^ 1] + bRow * 128 + bCol + 4) = pb1;
        __syncthreads();
        s ^= 1;
    }

    // last tile
    {
        const float* as = As[s];
        const float* bs = Bs[s];
#pragma unroll
        for (int kk = 0; kk < BK_; kk++) {
            float a[8], b[8];
            *reinterpret_cast<float4*>(a)     = *reinterpret_cast<const float4*>(as + kk * SAS_ + ty * 8);
            *reinterpret_cast<float4*>(a + 4) = *reinterpret_cast<const float4*>(as + kk * SAS_ + ty * 8 + 4);
            *reinterpret_cast<float4*>(b)     = *reinterpret_cast<const float4*>(bs + kk * 128 + tx * 8);
            *reinterpret_cast<float4*>(b + 4) = *reinterpret_cast<const float4*>(bs + kk * 128 + tx * 8 + 4);
#pragma unroll
            for (int i = 0; i < 8; i++)
#pragma unroll
                for (int j = 0; j < 8; j++) acc[i][j] = fmaf(a[i], b[j], acc[i][j]);
        }
    }

#pragma unroll
    for (int i = 0; i < 8; i++) {
        int r = blockRow + ty * 8 + i;
        if (r >= M) continue;
#pragma unroll
        for (int j = 0; j < 8; j++) {
            int c = blockCol + tx * 8 + j;
            float val = acc[i][j] + bias[c];
            if (act == 1) {
                // gelu(tanh approx), tanh via expf: tanh(u) = 1 - 2/(e^{2u}+1)
                float u = 0.7978845608028654f * (val + 0.044715f * val * val * val);
                float t = 1.f - 2.f / (__expf(2.f * u) + 1.f);
                val = 0.5f * val * (1.f + t);
            }
            C[(size_t)r * N + c] = val;
        }
    }
}

// ---------------- embedding + layernorm ----------------
__global__ __launch_bounds__(256) void embed_ln_kernel(
    const int* __restrict__ x, const int* __restrict__ segs,
    const float* __restrict__ we, const float* __restrict__ pe, const float* __restrict__ te,
    const float* __restrict__ lns, const float* __restrict__ lnb,
    float* __restrict__ hout)
{
    int s = blockIdx.x;
    int tid = threadIdx.x;
    __shared__ float buf[D_];
    __shared__ float red[256];
    int tok = x[s], seg = segs[s];
    float lsum = 0.f;
    for (int d = tid; d < D_; d += 256) {
        float v = we[(size_t)tok * D_ + d] + pe[(size_t)s * D_ + d] + te[(size_t)seg * D_ + d];
        buf[d] = v;
        lsum += v;
    }
    red[tid] = lsum; __syncthreads();
    for (int o = 128; o > 0; o >>= 1) { if (tid < o) red[tid] += red[tid + o]; __syncthreads(); }
    float mean = red[0] / D_;
    __syncthreads();
    float vsum = 0.f;
    for (int d = tid; d < D_; d += 256) { float t = buf[d] - mean; vsum += t * t; }
    red[tid] = vsum; __syncthreads();
    for (int o = 128; o > 0; o >>= 1) { if (tid < o) red[tid] += red[tid + o]; __syncthreads(); }
    float rstd = rsqrtf(red[0] / D_ + 1e-5f);
    for (int d = tid; d < D_; d += 256)
        hout[(size_t)s * D_ + d] = (buf[d] - mean) * rstd * lns[d] + lnb[d];
}

// ---------------- residual add + layernorm (in-place into h) ----------------
__global__ __launch_bounds__(256) void add_ln_kernel(
    float* __restrict__ h, const float* __restrict__ t,
    const float* __restrict__ lns, const float* __restrict__ lnb)
{
    int s = blockIdx.x;
    int tid = threadIdx.x;
    __shared__ float buf[D_];
    __shared__ float red[256];
    float lsum = 0.f;
    for (int d = tid; d < D_; d += 256) {
        float v = h[(size_t)s * D_ + d] + t[(size_t)s * D_ + d];
        buf[d] = v;
        lsum += v;
    }
    red[tid] = lsum; __syncthreads();
    for (int o = 128; o > 0; o >>= 1) { if (tid < o) red[tid] += red[tid + o]; __syncthreads(); }
    float mean = red[0] / D_;
    __syncthreads();
    float vsum = 0.f;
    for (int d = tid; d < D_; d += 256) { float x = buf[d] - mean; vsum += x * x; }
    red[tid] = vsum; __syncthreads();
    for (int o = 128; o > 0; o >>= 1) { if (tid < o) red[tid] += red[tid + o]; __syncthreads(); }
    float rstd = rsqrtf(red[0] / D_ + 1e-5f);
    for (int d = tid; d < D_; d += 256)
        h[(size_t)s * D_ + d] = (buf[d] - mean) * rstd * lns[d] + lnb[d];
}

// ---------------- global flags ----------------
__global__ void zero_flags_kernel(int* f)
{
    int i = blockIdx.x * 256 + threadIdx.x;
    if (i < S_) f[i] = 0;
}
__global__ void set_flags_kernel(const int* __restrict__ clss, int* f)
{
    if (threadIdx.x < NCLS_) f[clss[threadIdx.x]] = 1;
}
__global__ __launch_bounds__(256) void gather_rows_kernel(
    const float* __restrict__ h, const int* __restrict__ clss, float* __restrict__ hg)
{
    int c = blockIdx.x;
    int gp = clss[c];
    for (int d = threadIdx.x; d < D_; d += 256)
        hg[(size_t)c * D_ + d] = h[(size_t)gp * D_ + d];
}

// ================ tiled flash-style band + global-key attention ================
#define BKEY_ 128
#define NCH_  5
#define KS_   132
#define VS_   68
#define PS_   72
#define OF_Q  0
#define OF_K  4096
#define OF_V  (OF_K + 64*KS_)
#define OF_P  (OF_V + BKEY_*VS_)
#define OF_KV (OF_P + BKEY_*PS_)
#define OF_SC (OF_KV + BKEY_)
#define OF_SI (OF_SC + 64)
#define BAND_SMEM ((OF_SI + 64) * 4)

__global__ __launch_bounds__(256) void band_attn_tiled_kernel(
    const float* __restrict__ q, const float* __restrict__ k, const float* __restrict__ v,
    const int* __restrict__ clss, const int* __restrict__ mask_src, const int* __restrict__ glb,
    float* __restrict__ out)
{
    extern __shared__ float sm[];
    float* Qsd = sm + OF_Q;
    float* Ksd = sm + OF_K;
    float* Vs  = sm + OF_V;
    float* Pkq = sm + OF_P;
    int*   kvl = (int*)(sm + OF_KV);
    float* ssc = sm + OF_SC;
    float* sin_ = sm + OF_SI;

    const int c = blockIdx.x, hh = blockIdx.y;
    const int s0 = c * 64;
    const int t = threadIdx.x;
    const int w = t >> 5, lane = t & 31;

    for (int idx = t; idx < 64 * 16; idx += 256) {
        const int r = idx >> 4, seg = (idx & 15) * 4;
        const float4 qv = *reinterpret_cast<const float4*>(
            q + ((size_t)(s0 + r) * H_ + hh) * HD_ + seg);
        Qsd[(seg + 0) * 64 + r] = qv.x * 0.125f;
        Qsd[(seg + 1) * 64 + r] = qv.y * 0.125f;
        Qsd[(seg + 2) * 64 + r] = qv.z * 0.125f;
        Qsd[(seg + 3) * 64 + r] = qv.w * 0.125f;
    }

    float mstate = -1e30f, ssum = 0.f;
    float O[8][2];
#pragma unroll
    for (int j = 0; j < 8; j++) { O[j][0] = 0.f; O[j][1] = 0.f; }

    const int tq = t >> 4, tk = t & 15;
    const int r0 = tq * 4, kk0 = tk * 8;

    for (int ch = 0; ch < NCH_; ch++) {
        for (int idx = t; idx < BKEY_ * 16; idx += 256) {
            const int kr = idx >> 4, seg = (idx & 15) * 4;
            const int gi = ch * BKEY_ + kr;
            int p; int val;
            if (gi < NCLS_) {
                p = clss[gi];
                val = (mask_src[p] > 0);
            } else {
                p = s0 + gi - 320;
                val = (p >= 0 && p < S_);
                if (val) val = (mask_src[p] > 0) && (glb[p] == 0);
                if (!val) p = 0;
            }
            if ((idx & 15) == 0) kvl[kr] = val;
            const float4 kv = *reinterpret_cast<const float4*>(
                k + ((size_t)p * H_ + hh) * HD_ + seg);
            Ksd[(seg + 0) * KS_ + kr] = kv.x;
            Ksd[(seg + 1) * KS_ + kr] = kv.y;
            Ksd[(seg + 2) * KS_ + kr] = kv.z;
            Ksd[(seg + 3) * KS_ + kr] = kv.w;
            *reinterpret_cast<float4*>(Vs + kr * VS_ + seg) =
                *reinterpret_cast<const float4*>(v + ((size_t)p * H_ + hh) * HD_ + seg);
        }
        __syncthreads();

        float sc[4][8];
#pragma unroll
        for (int j = 0; j < 4; j++)
#pragma unroll
            for (int i = 0; i < 8; i++) sc[j][i] = 0.f;
#pragma unroll 8
        for (int d = 0; d < 64; d++) {
            const float4 a = *reinterpret_cast<const float4*>(Qsd + d * 64 + r0);
            const float4 b0 = *reinterpret_cast<const float4*>(Ksd + d * KS_ + kk0);
            const float4 b1 = *reinterpret_cast<const float4*>(Ksd + d * KS_ + kk0 + 4);
            const float aa[4] = {a.x, a.y, a.z, a.w};
            const float bb[8] = {b0.x, b0.y, b0.z, b0.w, b1.x, b1.y, b1.z, b1.w};
#pragma unroll
            for (int j = 0; j < 4; j++)
#pragma unroll
                for (int i = 0; i < 8; i++) sc[j][i] = fmaf(aa[j], bb[i], sc[j][i]);
        }
#pragma unroll
        for (int i = 0; i < 8; i++) {
            const int gi = ch * BKEY_ + kk0 + i;
            const int kvalid = kvl[kk0 + i];
#pragma unroll
            for (int j = 0; j < 4; j++) {
                const int r = r0 + j;
                const bool ok = kvalid &&
                    (gi < NCLS_ || (r >= gi - 576 && r <= gi - 64));
                Pkq[(kk0 + i) * PS_ + r] = ok ? sc[j][i] : -1e30f;
            }
        }
        __syncthreads();

        if (t < 64) {
            float mn = mstate;
            for (int kk = 0; kk < BKEY_; kk++) mn = fmaxf(mn, Pkq[kk * PS_ + t]);
            const float scale = (mn <= -1e29f) ? 1.f : __expf(mstate - mn);
            float ls = 0.f;
            for (int kk = 0; kk < BKEY_; kk++) {
                const float sv = Pkq[kk * PS_ + t];
                const float pv = (sv <= -1e29f) ? 0.f : __expf(sv - mn);
                Pkq[kk * PS_ + t] = pv;
                ls += pv;
            }
            ssum = ssum * scale + ls;
            mstate = mn;
            ssc[t] = scale;
        }
        __syncthreads();

        {
#pragma unroll
            for (int j = 0; j < 8; j++) {
                const float scj = ssc[w * 8 + j];
                O[j][0] *= scj; O[j][1] *= scj;
            }
            for (int kk = 0; kk < BKEY_; kk++) {
                const float4 pa = *reinterpret_cast<const float4*>(Pkq + kk * PS_ + w * 8);
                const float4 pb = *reinterpret_cast<const float4*>(Pkq + kk * PS_ + w * 8 + 4);
                const float v0 = Vs[kk * VS_ + lane];
                const float v1 = Vs[kk * VS_ + lane + 32];
                O[0][0] = fmaf(pa.x, v0, O[0][0]); O[0][1] = fmaf(pa.x, v1, O[0][1]);
                O[1][0] = fmaf(pa.y, v0, O[1][0]); O[1][1] = fmaf(pa.y, v1, O[1][1]);
                O[2][0] = fmaf(pa.z, v0, O[2][0]); O[2][1] = fmaf(pa.z, v1, O[2][1]);
                O[3][0] = fmaf(pa.w, v0, O[3][0]); O[3][1] = fmaf(pa.w, v1, O[3][1]);
                O[4][0] = fmaf(pb.x, v0, O[4][0]); O[4][1] = fmaf(pb.x, v1, O[4][1]);
                O[5][0] = fmaf(pb.y, v0, O[5][0]); O[5][1] = fmaf(pb.y, v1, O[5][1]);
                O[6][0] = fmaf(pb.z, v0, O[6][0]); O[6][1] = fmaf(pb.z, v1, O[6][1]);
                O[7][0] = fmaf(pb.w, v0, O[7][0]); O[7][1] = fmaf(pb.w, v1, O[7][1]);
            }
        }
        __syncthreads();
    }

    if (t < 64) sin_[t] = 1.f / ssum;
    __syncthreads();
#pragma unroll
    for (int j = 0; j < 8; j++) {
        const int qr = w * 8 + j;
        const float inv = sin_[qr];
        float* op = out + ((size_t)(s0 + qr) * H_ + hh) * HD_;
        op[lane]      = O[j][0] * inv;
        op[lane + 32] = O[j][1] * inv;
    }
}

// ---------------- global-query full attention: one block per (c, head) ----------------
__global__ __launch_bounds__(256) void glb_attn_kernel(
    const float* __restrict__ qg, const float* __restrict__ kg, const float* __restrict__ vg,
    const int* __restrict__ clss, const int* __restrict__ mask_src,
    float* __restrict__ out)
{
    const int c = blockIdx.x;
    const int h = blockIdx.y;
    __shared__ float qs[HD_];
    __shared__ float sc[S_];
    __shared__ float red[256];
    const int tid = threadIdx.x;
    const int lane = tid & 31;
    const int w = tid >> 5;

    if (tid < HD_) qs[tid] = qg[((size_t)c * H_ + h) * HD_ + tid] * 0.125f;
    __syncthreads();

    for (int p = w; p < S_; p += 8) {
        const float* kp = kg + ((size_t)p * H_ + h) * HD_;
        float sdot = qs[lane] * kp[lane] + qs[lane + 32] * kp[lane + 32];
#pragma unroll
        for (int o = 16; o > 0; o >>= 1) sdot += __shfl_xor_sync(0xffffffffu, sdot, o);
        if (lane == 0) sc[p] = (mask_src[p] > 0) ? sdot : -1e30f;
    }
    __syncthreads();

    float m = -1e30f;
    for (int p = tid; p < S_; p += 256) m = fmaxf(m, sc[p]);
    red[tid] = m; __syncthreads();
    for (int o = 128; o > 0; o >>= 1) { if (tid < o) red[tid] = fmaxf(red[tid], red[tid + o]); __syncthreads(); }
    m = red[0];
    __syncthreads();
    float sum = 0.f;
    for (int p = tid; p < S_; p += 256) { float e = __expf(sc[p] - m); sc[p] = e; sum += e; }
    red[tid] = sum; __syncthreads();
    for (int o = 128; o > 0; o >>= 1) { if (tid < o) red[tid] += red[tid + o]; __syncthreads(); }
    float inv = 1.f / red[0];
    __syncthreads();

    int d = tid & 63, quarter = tid >> 6;
    float acc = 0.f;
    for (int p = quarter; p < S_; p += 4)
        acc += sc[p] * vg[((size_t)p * H_ + h) * HD_ + d];
    red[tid] = acc; __syncthreads();
    if (tid < 64) {
        float o = (red[tid] + red[tid + 64] + red[tid + 128] + red[tid + 192]) * inv;
        int gp = clss[c];
        out[((size_t)gp * H_ + h) * HD_ + tid] = o;
    }
}

// ---------------- driver ----------------
static void run_gemm(const float* A, const float* B, const float* bias, float* C,
                     int M, int N, int K, int act)
{
    dim3 grid(N / 128, (M + 127) / 128);
    sgemm_kernel<<<grid, 256>>>(A, B, bias, C, M, N, K, act);
}

extern "C" void kernel_launch(void* const* d_in, const int* in_sizes, int n_in,
                              void* d_out, int out_size)
{
    (void)in_sizes; (void)n_in;
    const int*   x        = (const int*)d_in[0];
    const int*   mask_src = (const int*)d_in[1];
    const int*   clss     = (const int*)d_in[2];
    const int*   segs     = (const int*)d_in[3];
    const float* word_emb = (const float*)d_in[4];
    const float* pos_emb  = (const float*)d_in[5];
    const float* type_emb = (const float*)d_in[6];
    const float* ln_e_s   = (const float*)d_in[7];
    const float* ln_e_b   = (const float*)d_in[8];
    const float* Wq  = (const float*)d_in[9];   const float* bq  = (const float*)d_in[10];
    const float* Wk  = (const float*)d_in[11];  const float* bk  = (const float*)d_in[12];
    const float* Wv  = (const float*)d_in[13];  const float* bv  = (const float*)d_in[14];
    const float* Wqg = (const float*)d_in[15];  const float* bqg = (const float*)d_in[16];
    const float* Wkg = (const float*)d_in[17];  const float* bkg = (const float*)d_in[18];
    const float* Wvg = (const float*)d_in[19];  const float* bvg = (const float*)d_in[20];
    const float* Wo  = (const float*)d_in[21];  const float* bo  = (const float*)d_in[22];
    const float* ln1_s = (const float*)d_in[23]; const float* ln1_b = (const float*)d_in[24];
    const float* Wf1 = (const float*)d_in[25];  const float* bf1 = (const float*)d_in[26];
    const float* Wf2 = (const float*)d_in[27];  const float* bf2 = (const float*)d_in[28];
    const float* ln2_s = (const float*)d_in[29]; const float* ln2_b = (const float*)d_in[30];

    float *h, *q, *k, *v, *kg, *vg, *outb, *tmp, *ff, *hg, *qg;
    int* glb;
    cudaGetSymbolAddress((void**)&h,    g_h);
    cudaGetSymbolAddress((void**)&q,    g_q);
    cudaGetSymbolAddress((void**)&k,    g_k);
    cudaGetSymbolAddress((void**)&v,    g_v);
    cudaGetSymbolAddress((void**)&kg,   g_kg);
    cudaGetSymbolAddress((void**)&vg,   g_vg);
    cudaGetSymbolAddress((void**)&outb, g_out);
    cudaGetSymbolAddress((void**)&tmp,  g_tmp);
    cudaGetSymbolAddress((void**)&ff,   g_ff);
    cudaGetSymbolAddress((void**)&hg,   g_hg);
    cudaGetSymbolAddress((void**)&qg,   g_qg);
    cudaGetSymbolAddress((void**)&glb,  g_glb);

    cudaFuncSetAttribute(band_attn_tiled_kernel,
                         cudaFuncAttributeMaxDynamicSharedMemorySize, BAND_SMEM);

    // embedding + LN
    embed_ln_kernel<<<S_, 256>>>(x, segs, word_emb, pos_emb, type_emb, ln_e_s, ln_e_b, h);

    // global flags
    zero_flags_kernel<<<(S_ + 255) / 256, 256>>>(glb);
    set_flags_kernel<<<1, 64>>>(clss, glb);

    const size_t DD = (size_t)D_ * D_;
    for (int l = 0; l < LAYERS_; l++) {
        // Q K V projections
        run_gemm(h, Wq + l * DD, bq + l * D_, q, S_, D_, D_, 0);
        run_gemm(h, Wk + l * DD, bk + l * D_, k, S_, D_, D_, 0);
        run_gemm(h, Wv + l * DD, bv + l * D_, v, S_, D_, D_, 0);

        // tiled band + global-key attention (writes all rows of outb)
        band_attn_tiled_kernel<<<dim3(S_ / 64, H_), 256, BAND_SMEM>>>(
            q, k, v, clss, mask_src, glb, outb);

        // global-query path
        gather_rows_kernel<<<NCLS_, 256>>>(h, clss, hg);
        sgemm_kernel<<<dim3(D_ / 128, 1), 256>>>(hg, Wqg + l * DD, bqg + l * D_, qg, NCLS_, D_, D_, 0);
        run_gemm(h, Wkg + l * DD, bkg + l * D_, kg, S_, D_, D_, 0);
        run_gemm(h, Wvg + l * DD, bvg + l * D_, vg, S_, D_, D_, 0);
        glb_attn_kernel<<<dim3(NCLS_, H_), 256>>>(qg, kg, vg, clss, mask_src, outb);

        // output projection + residual LN
        run_gemm(outb, Wo + l * DD, bo + l * D_, tmp, S_, D_, D_, 0);
        add_ln_kernel<<<S_, 256>>>(h, tmp, ln1_s + l * D_, ln1_b + l * D_);

        // feed-forward
        run_gemm(h,  Wf1 + (size_t)l * D_ * FF_, bf1 + l * FF_, ff,  S_, FF_, D_, 1);
        run_gemm(ff, Wf2 + (size_t)l * D_ * FF_, bf2 + l * D_,  tmp, S_, D_, FF_, 0);
        add_ln_kernel<<<S_, 256>>>(h, tmp, ln2_s + l * D_, ln2_b + l * D_);
    }

    cudaMemcpyAsync(d_out, h, (size_t)out_size * sizeof(float), cudaMemcpyDeviceToDevice);
}